// round 17
// baseline (speedup 1.0000x reference)
#include <cuda_runtime.h>
#include <cuda_bf16.h>
#include <cuda_fp16.h>
#include <cstdint>

#define BB 4
#define CC 512
#define CI 256
#define NN 4096
#define QT 128

typedef unsigned long long u64;
typedef unsigned int u32;

// ---------------- device scratch (no allocation allowed) ----------------
__device__ __align__(256) __nv_bfloat16 g_xt_hi[BB * NN * CC]; // x^T [b][n][c]
__device__ __align__(256) __nv_bfloat16 g_xt_lo[BB * NN * CC];
__device__ __align__(256) __nv_bfloat16 g_wt_hi[CI * CC];
__device__ __align__(256) __nv_bfloat16 g_wt_lo[CI * CC];
__device__ __align__(256) __nv_bfloat16 g_wp_hi[CI * CC];
__device__ __align__(256) __nv_bfloat16 g_wp_lo[CI * CC];
__device__ __align__(256) __nv_bfloat16 g_wg_hi[CI * CC];
__device__ __align__(256) __nv_bfloat16 g_wg_lo[CI * CC];
__device__ __align__(256) __nv_bfloat16 g_wo_hi[CC * CI];
__device__ __align__(256) __nv_bfloat16 g_wo_lo[CC * CI];
__device__ __align__(256) __nv_bfloat16 g_th_hi[BB * NN * CI]; // theta [b][n][o]
__device__ __align__(256) __nv_bfloat16 g_th_lo[BB * NN * CI];
__device__ __align__(256) __nv_bfloat16 g_ph_hi[BB * NN * CI]; // phi   [b][n][o]
__device__ __align__(256) __nv_bfloat16 g_ph_lo[BB * NN * CI];
__device__ __align__(256) __half       g_g16 [BB * CI * NN];   // g     [b][o][n] fp16
__device__ __align__(256) __nv_bfloat16 g_y_hi[BB * NN * CI];  // y     [b][n][o]
__device__ __align__(256) __nv_bfloat16 g_y_lo[BB * NN * CI];

// ---------------- PTX helpers ----------------
__device__ __forceinline__ void cp16(u32 dst, const void* src) {
    asm volatile("cp.async.ca.shared.global [%0], [%1], 16;" :: "r"(dst), "l"(src));
}
#define CP_COMMIT() asm volatile("cp.async.commit_group;" ::: "memory")
#define CP_WAIT0()  asm volatile("cp.async.wait_group 0;" ::: "memory")

__device__ __forceinline__ u32 smem_u32(const void* p) {
    u32 a;
    asm("{ .reg .u64 t; cvta.to.shared.u64 t, %1; cvt.u32.u64 %0, t; }" : "=r"(a) : "l"(p));
    return a;
}
__device__ __forceinline__ void mma_bf16(float c[4], const u32 a[4], const u32 b[2]) {
    asm volatile("mma.sync.aligned.m16n8k16.row.col.f32.bf16.bf16.f32 "
                 "{%0,%1,%2,%3}, {%4,%5,%6,%7}, {%8,%9}, {%0,%1,%2,%3};"
                 : "+f"(c[0]), "+f"(c[1]), "+f"(c[2]), "+f"(c[3])
                 : "r"(a[0]), "r"(a[1]), "r"(a[2]), "r"(a[3]), "r"(b[0]), "r"(b[1]));
}
__device__ __forceinline__ void mma_f16(float c[4], const u32 a[4], const u32 b[2]) {
    asm volatile("mma.sync.aligned.m16n8k16.row.col.f32.f16.f16.f32 "
                 "{%0,%1,%2,%3}, {%4,%5,%6,%7}, {%8,%9}, {%0,%1,%2,%3};"
                 : "+f"(c[0]), "+f"(c[1]), "+f"(c[2]), "+f"(c[3])
                 : "r"(a[0]), "r"(a[1]), "r"(a[2]), "r"(a[3]), "r"(b[0]), "r"(b[1]));
}
__device__ __forceinline__ u32 pack_bf2(float a, float b) {
    u32 ra = (u32)__bfloat16_as_ushort(__float2bfloat16_rn(a));
    u32 rb = (u32)__bfloat16_as_ushort(__float2bfloat16_rn(b));
    return ra | (rb << 16);
}
__device__ __forceinline__ float bf_hi(float v) {
    return __bfloat162float(__float2bfloat16_rn(v));
}
__device__ __forceinline__ u32 pack_h2(float a, float b) {
    __half2 h = __floats2half2_rn(a, b);
    return *(u32*)&h;
}

// ===========================================================================
// Kernel 0a: transpose + split x [b][c][n] fp32 -> x_t hi/lo [b][n][c] bf16
// ===========================================================================
__global__ __launch_bounds__(256) void xsplit_kernel(const float* __restrict__ x)
{
    __shared__ float t[32][33];
    int b  = blockIdx.z;
    int n0 = blockIdx.x * 32;
    int c0 = blockIdx.y * 32;
    int tx = threadIdx.x & 31, ty = threadIdx.x >> 5;
    const float* xb = x + (size_t)b * CC * NN;
    #pragma unroll
    for (int j = 0; j < 4; j++)
        t[ty + 8 * j][tx] = xb[(size_t)(c0 + ty + 8 * j) * NN + n0 + tx];
    __syncthreads();
    size_t base = (size_t)b * NN * CC;
    #pragma unroll
    for (int j = 0; j < 4; j++) {
        int n = n0 + ty + 8 * j;
        float v = t[tx][ty + 8 * j];
        float h = bf_hi(v);
        g_xt_hi[base + (size_t)n * CC + c0 + tx] = __float2bfloat16_rn(h);
        g_xt_lo[base + (size_t)n * CC + c0 + tx] = __float2bfloat16_rn(v - h);
    }
}

// ===========================================================================
// Kernel 0b: split the 4 weight matrices into bf16 hi/lo
// ===========================================================================
__global__ __launch_bounds__(256) void wsplit_kernel(
    const float* __restrict__ wt, const float* __restrict__ wp,
    const float* __restrict__ wg, const float* __restrict__ wo)
{
    int idx = blockIdx.x * 256 + threadIdx.x;
    int which = blockIdx.y;
    const float* src = (which == 0) ? wt : (which == 1) ? wp : (which == 2) ? wg : wo;
    __nv_bfloat16* dh = (which == 0) ? g_wt_hi : (which == 1) ? g_wp_hi : (which == 2) ? g_wg_hi : g_wo_hi;
    __nv_bfloat16* dl = (which == 0) ? g_wt_lo : (which == 1) ? g_wp_lo : (which == 2) ? g_wg_lo : g_wo_lo;
    float v = src[idx];
    float h = bf_hi(v);
    dh[idx] = __float2bfloat16_rn(h);
    dl[idx] = __float2bfloat16_rn(v - h);
}

// ---- shared stage geometry for the mma GEMM kernels ----
#define ST_ALO 18432
#define ST_BHI 36864
#define ST_BLO 55296
#define ST_SZ  73728
#define GEMM_SMEM (2 * ST_SZ)

// ===========================================================================
// Kernel 1: projections via mma.sync, 3-pass bf16 hi/lo. (unchanged R15)
// ===========================================================================
__global__ __launch_bounds__(256, 1) void proj_mma(
    const float* __restrict__ bt, const float* __restrict__ bp,
    const float* __restrict__ bg)
{
    extern __shared__ __align__(1024) char sm[];
    u32 dyn = smem_u32(sm);
    int id = blockIdx.x, b = blockIdx.y;
    int mat = id >> 6, sub = id & 63;
    int tid = threadIdx.x, lane = tid & 31, wid = tid >> 5;
    int gid = lane >> 2, tig = lane & 3;

    const __nv_bfloat16 *Ahi, *Alo, *Bhi, *Blo;
    const float* bias;
    int mt, ot;
    if (mat < 2) {
        mt = sub & 31; ot = sub >> 5;
        Ahi = g_xt_hi + (size_t)b * NN * CC + (size_t)(mt * 128) * CC;
        Alo = g_xt_lo + (size_t)b * NN * CC + (size_t)(mt * 128) * CC;
        Bhi = (mat ? g_wp_hi : g_wt_hi) + (size_t)(ot * 128) * CC;
        Blo = (mat ? g_wp_lo : g_wt_lo) + (size_t)(ot * 128) * CC;
        bias = mat ? bp : bt;
    } else {
        mt = sub >> 5; ot = sub & 31;
        Ahi = g_wg_hi + (size_t)(mt * 128) * CC;
        Alo = g_wg_lo + (size_t)(mt * 128) * CC;
        Bhi = g_xt_hi + (size_t)b * NN * CC + (size_t)(ot * 128) * CC;
        Blo = g_xt_lo + (size_t)b * NN * CC + (size_t)(ot * 128) * CC;
        bias = bg;
    }

    auto stage_load = [&](int kc, int buf) {
        u32 base = dyn + buf * ST_SZ;
        #pragma unroll
        for (int i = 0; i < 4; i++) {
            int idx2 = tid + i * 256;
            int r = idx2 >> 3, c = idx2 & 7;
            u32 o = r * 144 + c * 16;
            cp16(base + o,          Ahi + (size_t)r * CC + kc + c * 8);
            cp16(base + ST_ALO + o, Alo + (size_t)r * CC + kc + c * 8);
            cp16(base + ST_BHI + o, Bhi + (size_t)r * CC + kc + c * 8);
            cp16(base + ST_BLO + o, Blo + (size_t)r * CC + kc + c * 8);
        }
    };

    float acc[16][4];
    #pragma unroll
    for (int nb = 0; nb < 16; nb++)
        #pragma unroll
        for (int j = 0; j < 4; j++) acc[nb][j] = 0.f;

    stage_load(0, 0);
    CP_COMMIT();

    int m0 = wid * 16;
    for (int kc8 = 0; kc8 < 8; kc8++) {
        CP_WAIT0();
        __syncthreads();
        if (kc8 < 7) { stage_load((kc8 + 1) * 64, (kc8 + 1) & 1); CP_COMMIT(); }

        u32 sb = (kc8 & 1) * ST_SZ;
        #pragma unroll
        for (int ks = 0; ks < 4; ks++) {
            u32 a0 = sb + (m0 + gid) * 144 + (ks * 16 + 2 * tig) * 2;
            u32 ah[4], al[4];
            ah[0] = *(const u32*)(sm + a0);
            ah[1] = *(const u32*)(sm + a0 + 8 * 144);
            ah[2] = *(const u32*)(sm + a0 + 16);
            ah[3] = *(const u32*)(sm + a0 + 8 * 144 + 16);
            al[0] = *(const u32*)(sm + a0 + ST_ALO);
            al[1] = *(const u32*)(sm + a0 + ST_ALO + 8 * 144);
            al[2] = *(const u32*)(sm + a0 + ST_ALO + 16);
            al[3] = *(const u32*)(sm + a0 + ST_ALO + 8 * 144 + 16);
            #pragma unroll
            for (int nb = 0; nb < 16; nb++) {
                u32 bo = sb + ST_BHI + (nb * 8 + gid) * 144 + (ks * 16 + 2 * tig) * 2;
                u32 bh[2], bl[2];
                bh[0] = *(const u32*)(sm + bo);
                bh[1] = *(const u32*)(sm + bo + 16);
                bl[0] = *(const u32*)(sm + bo + (ST_BLO - ST_BHI));
                bl[1] = *(const u32*)(sm + bo + (ST_BLO - ST_BHI) + 16);
                mma_bf16(acc[nb], ah, bh);
                mma_bf16(acc[nb], ah, bl);
                mma_bf16(acc[nb], al, bh);
            }
        }
    }

    if (mat < 2) {
        __nv_bfloat16* oh = (mat ? g_ph_hi : g_th_hi) + (size_t)b * NN * CI;
        __nv_bfloat16* ol = (mat ? g_ph_lo : g_th_lo) + (size_t)b * NN * CI;
        int nrow = mt * 128 + m0 + gid;
        #pragma unroll
        for (int nb = 0; nb < 16; nb++) {
            int o = ot * 128 + nb * 8 + 2 * tig;
            float b0 = bias[o], b1 = bias[o + 1];
            float v0 = acc[nb][0] + b0, v1 = acc[nb][1] + b1;
            float v2 = acc[nb][2] + b0, v3 = acc[nb][3] + b1;
            float h0 = bf_hi(v0), h1 = bf_hi(v1), h2 = bf_hi(v2), h3 = bf_hi(v3);
            *(u32*)(oh + (size_t)nrow * CI + o)       = pack_bf2(h0, h1);
            *(u32*)(ol + (size_t)nrow * CI + o)       = pack_bf2(v0 - h0, v1 - h1);
            *(u32*)(oh + (size_t)(nrow + 8) * CI + o) = pack_bf2(h2, h3);
            *(u32*)(ol + (size_t)(nrow + 8) * CI + o) = pack_bf2(v2 - h2, v3 - h3);
        }
    } else {
        __half* gb = g_g16 + (size_t)b * CI * NN;
        int orow = mt * 128 + m0 + gid;
        float b0 = bias[orow], b8 = bias[orow + 8];
        #pragma unroll
        for (int nb = 0; nb < 16; nb++) {
            int n = ot * 128 + nb * 8 + 2 * tig;
            *(u32*)(gb + (size_t)orow * NN + n)       = pack_h2(acc[nb][0] + b0, acc[nb][1] + b0);
            *(u32*)(gb + (size_t)(orow + 8) * NN + n) = pack_h2(acc[nb][2] + b8, acc[nb][3] + b8);
        }
    }
}

// ---- attention smem layout ----
#define TH_HI_OFF 0
#define TH_LO_OFF 67584
#define PH_OFF    135168
#define PH_BUF    18432
#define PH_LO     9216
#define P_OFF     172032
#define G_OFF     190464
#define MP_OFF    227328   // Mpart [2][128] f32
#define LP_OFF    228352   // Lpart [2][128] f32
#define DYN_SMEM  229376

// ===========================================================================
// Kernel 2: mma.sync flash attention, rebalanced 4Mx2N warp tiling.
// S phase: warp (wm, wn): q rows [wm*32,+32), keys [wn*32,+32).
// PV phase: warp (wm, wn): q rows [wm*32,+32), o cols [wn*128,+128).
// ===========================================================================
__global__ __launch_bounds__(256, 1) void attn_kernel()
{
    extern __shared__ __align__(1024) char dsm[];
    u32 dyn = smem_u32(dsm);

    int b    = blockIdx.y;
    int q0   = blockIdx.x * QT;
    int tid  = threadIdx.x;
    int lane = tid & 31;
    int wid  = tid >> 5;
    int wm   = wid & 3;        // 0..3 : q-row group of 32
    int wn   = wid >> 2;       // 0..1 : key half (S) / o half (PV)
    int gid  = lane >> 2;
    int tig  = lane & 3;

    const __nv_bfloat16* th_hi = g_th_hi + (size_t)b * NN * CI;
    const __nv_bfloat16* th_lo = g_th_lo + (size_t)b * NN * CI;
    const __nv_bfloat16* ph_hi = g_ph_hi + (size_t)b * NN * CI;
    const __nv_bfloat16* ph_lo = g_ph_lo + (size_t)b * NN * CI;
    const __half*        gg    = g_g16  + (size_t)b * CI * NN;

    for (int idx = tid; idx < 4096; idx += 256) {
        int r = idx >> 5, c = idx & 31;
        *(uint4*)(dsm + TH_HI_OFF + r * 528 + c * 16) =
            *(const uint4*)(th_hi + (size_t)(q0 + r) * CI + c * 8);
        *(uint4*)(dsm + TH_LO_OFF + r * 528 + c * 16) =
            *(const uint4*)(th_lo + (size_t)(q0 + r) * CI + c * 8);
    }

    auto issue_phi = [&](int t_, int oc_, int buf) {
        #pragma unroll
        for (int i = 0; i < 2; i++) {
            int idx = tid + i * 256;
            int r = idx >> 3, c = idx & 7;
            u32 d = dyn + PH_OFF + buf * PH_BUF + r * 144 + c * 16;
            cp16(d, ph_hi + (size_t)(t_ * 64 + r) * CI + oc_ * 64 + c * 8);
            cp16(d + PH_LO, ph_lo + (size_t)(t_ * 64 + r) * CI + oc_ * 64 + c * 8);
        }
    };
    auto issue_g = [&](int t_) {
        #pragma unroll
        for (int i = 0; i < 8; i++) {
            int idx = tid + i * 256;
            int r = idx >> 3, c = idx & 7;
            cp16(dyn + G_OFF + r * 144 + c * 16,
                 gg + (size_t)r * NN + t_ * 64 + c * 8);
        }
    };

    issue_phi(0, 0, 0);
    CP_COMMIT();

    // 4 row slots per lane: s = mt*2 + h -> row wm*32 + mt*16 + gid + h*8
    float M[4], lloc[4];
    #pragma unroll
    for (int s = 0; s < 4; s++) { M[s] = -1e30f; lloc[s] = 0.f; }

    float yacc[2][16][4];   // [mt][nt][c]
    #pragma unroll
    for (int mt = 0; mt < 2; mt++)
        #pragma unroll
        for (int nt = 0; nt < 16; nt++)
            #pragma unroll
            for (int j = 0; j < 4; j++) yacc[mt][nt][j] = 0.f;

    float* Mpart = (float*)(dsm + MP_OFF);   // [2][128]
    float* Lpart = (float*)(dsm + LP_OFF);   // [2][128]

    for (int t = 0; t < 64; t++) {
        float sf[2][4][4];   // [mt][nb][c]
        #pragma unroll
        for (int mt = 0; mt < 2; mt++)
            #pragma unroll
            for (int nb = 0; nb < 4; nb++)
                #pragma unroll
                for (int j = 0; j < 4; j++) sf[mt][nb][j] = 0.f;

        // ===== S = theta . phi^T over 4 o-chunks of 64 =====
        for (int oc = 0; oc < 4; oc++) {
            CP_WAIT0();
            __syncthreads();
            if (oc < 3) issue_phi(t, oc + 1, (oc + 1) & 1);
            else { issue_g(t); if (t < 63) issue_phi(t + 1, 0, 0); }
            CP_COMMIT();

            u32 phb = (u32)(PH_OFF + (oc & 1) * PH_BUF);
            #pragma unroll
            for (int ks = 0; ks < 4; ks++) {
                u32 acol = (oc * 64 + ks * 16 + 2 * tig) * 2;
                u32 ah[2][4], al[2][4];
                #pragma unroll
                for (int mt = 0; mt < 2; mt++) {
                    u32 a0 = TH_HI_OFF + (wm * 32 + mt * 16 + gid) * 528 + acol;
                    ah[mt][0] = *(const u32*)(dsm + a0);
                    ah[mt][1] = *(const u32*)(dsm + a0 + 8 * 528);
                    ah[mt][2] = *(const u32*)(dsm + a0 + 16);
                    ah[mt][3] = *(const u32*)(dsm + a0 + 8 * 528 + 16);
                    al[mt][0] = *(const u32*)(dsm + a0 + (TH_LO_OFF - TH_HI_OFF));
                    al[mt][1] = *(const u32*)(dsm + a0 + (TH_LO_OFF - TH_HI_OFF) + 8 * 528);
                    al[mt][2] = *(const u32*)(dsm + a0 + (TH_LO_OFF - TH_HI_OFF) + 16);
                    al[mt][3] = *(const u32*)(dsm + a0 + (TH_LO_OFF - TH_HI_OFF) + 8 * 528 + 16);
                }
                #pragma unroll
                for (int nb = 0; nb < 4; nb++) {
                    u32 boff = phb + (wn * 32 + nb * 8 + gid) * 144 + (ks * 16 + 2 * tig) * 2;
                    u32 bh[2], bl[2];
                    bh[0] = *(const u32*)(dsm + boff);
                    bh[1] = *(const u32*)(dsm + boff + 16);
                    bl[0] = *(const u32*)(dsm + boff + PH_LO);
                    bl[1] = *(const u32*)(dsm + boff + PH_LO + 16);
                    #pragma unroll
                    for (int mt = 0; mt < 2; mt++) {
                        mma_bf16(sf[mt][nb], ah[mt], bh);
                        mma_bf16(sf[mt][nb], ah[mt], bl);
                        mma_bf16(sf[mt][nb], al[mt], bh);
                    }
                }
            }
        }

        // ===== cross-warp row max =====
        float mx[4];
        #pragma unroll
        for (int mt = 0; mt < 2; mt++) {
            float a0 = -1e30f, a1 = -1e30f;
            #pragma unroll
            for (int nb = 0; nb < 4; nb++) {
                a0 = fmaxf(a0, fmaxf(sf[mt][nb][0], sf[mt][nb][1]));
                a1 = fmaxf(a1, fmaxf(sf[mt][nb][2], sf[mt][nb][3]));
            }
            mx[mt * 2 + 0] = a0;
            mx[mt * 2 + 1] = a1;
        }
        #pragma unroll
        for (int s = 0; s < 4; s++) {
            mx[s] = fmaxf(mx[s], __shfl_xor_sync(0xffffffffu, mx[s], 1));
            mx[s] = fmaxf(mx[s], __shfl_xor_sync(0xffffffffu, mx[s], 2));
        }
        if (tig == 0) {
            #pragma unroll
            for (int s = 0; s < 4; s++) {
                int row = wm * 32 + (s >> 1) * 16 + gid + (s & 1) * 8;
                Mpart[wn * 128 + row] = mx[s];
            }
        }
        __syncthreads();
        #pragma unroll
        for (int s = 0; s < 4; s++) {
            int row = wm * 32 + (s >> 1) * 16 + gid + (s & 1) * 8;
            mx[s] = fmaxf(Mpart[row], Mpart[128 + row]);
        }

        // online rescale (branchless)
        float sc[4];
        #pragma unroll
        for (int s = 0; s < 4; s++) {
            float Mn = fmaxf(M[s], mx[s]);
            sc[s] = __expf(M[s] - Mn);
            M[s] = Mn;
            lloc[s] *= sc[s];
        }
        #pragma unroll
        for (int mt = 0; mt < 2; mt++)
            #pragma unroll
            for (int nt = 0; nt < 16; nt++) {
                yacc[mt][nt][0] *= sc[mt * 2];     yacc[mt][nt][1] *= sc[mt * 2];
                yacc[mt][nt][2] *= sc[mt * 2 + 1]; yacc[mt][nt][3] *= sc[mt * 2 + 1];
            }

        // exp + write P (fp16)
        #pragma unroll
        for (int mt = 0; mt < 2; mt++) {
            int r0 = wm * 32 + mt * 16 + gid;
            u32 pb0 = P_OFF + r0 * 144 + (wn * 32 + 2 * tig) * 2;
            u32 pb1 = pb0 + 8 * 144;
            #pragma unroll
            for (int nb = 0; nb < 4; nb++) {
                float p0 = __expf(sf[mt][nb][0] - M[mt * 2]);
                float p1 = __expf(sf[mt][nb][1] - M[mt * 2]);
                float p2 = __expf(sf[mt][nb][2] - M[mt * 2 + 1]);
                float p3 = __expf(sf[mt][nb][3] - M[mt * 2 + 1]);
                lloc[mt * 2]     += p0 + p1;
                lloc[mt * 2 + 1] += p2 + p3;
                *(u32*)(dsm + pb0 + nb * 16) = pack_h2(p0, p1);
                *(u32*)(dsm + pb1 + nb * 16) = pack_h2(p2, p3);
            }
        }

        CP_WAIT0();
        __syncthreads();

        // ===== Y += P . G  (warp: rows wm*32+32, o cols wn*128..+128) =====
        #pragma unroll
        for (int ks = 0; ks < 4; ks++) {
            u32 ap[2][4];
            #pragma unroll
            for (int mt = 0; mt < 2; mt++) {
                u32 pa = P_OFF + (wm * 32 + mt * 16 + gid) * 144 + (ks * 16 + 2 * tig) * 2;
                ap[mt][0] = *(const u32*)(dsm + pa);
                ap[mt][1] = *(const u32*)(dsm + pa + 8 * 144);
                ap[mt][2] = *(const u32*)(dsm + pa + 16);
                ap[mt][3] = *(const u32*)(dsm + pa + 8 * 144 + 16);
            }
            #pragma unroll
            for (int nt = 0; nt < 16; nt++) {
                u32 gb = G_OFF + (wn * 128 + nt * 8 + gid) * 144 + (ks * 16 + 2 * tig) * 2;
                u32 bg[2];
                bg[0] = *(const u32*)(dsm + gb);
                bg[1] = *(const u32*)(dsm + gb + 16);
                mma_f16(yacc[0][nt], ap[0], bg);
                mma_f16(yacc[1][nt], ap[1], bg);
            }
        }
        __syncthreads();
    }

    // ===== epilogue: combine l across tig + wn, normalize, write y hi/lo ====
    #pragma unroll
    for (int s = 0; s < 4; s++) {
        lloc[s] += __shfl_xor_sync(0xffffffffu, lloc[s], 1);
        lloc[s] += __shfl_xor_sync(0xffffffffu, lloc[s], 2);
    }
    if (tig == 0) {
        #pragma unroll
        for (int s = 0; s < 4; s++) {
            int row = wm * 32 + (s >> 1) * 16 + gid + (s & 1) * 8;
            Lpart[wn * 128 + row] = lloc[s];
        }
    }
    __syncthreads();
    float inv[4];
    #pragma unroll
    for (int s = 0; s < 4; s++) {
        int row = wm * 32 + (s >> 1) * 16 + gid + (s & 1) * 8;
        inv[s] = 1.f / (Lpart[row] + Lpart[128 + row]);
    }

    __nv_bfloat16* yh = g_y_hi + (size_t)b * NN * CI;
    __nv_bfloat16* yl = g_y_lo + (size_t)b * NN * CI;
    #pragma unroll
    for (int mt = 0; mt < 2; mt++) {
        int r0 = q0 + wm * 32 + mt * 16 + gid;
        #pragma unroll
        for (int nt = 0; nt < 16; nt++) {
            int o = wn * 128 + nt * 8 + 2 * tig;
            float v0 = yacc[mt][nt][0] * inv[mt * 2],     v1 = yacc[mt][nt][1] * inv[mt * 2];
            float v2 = yacc[mt][nt][2] * inv[mt * 2 + 1], v3 = yacc[mt][nt][3] * inv[mt * 2 + 1];
            float h0 = bf_hi(v0), h1 = bf_hi(v1), h2 = bf_hi(v2), h3 = bf_hi(v3);
            *(u32*)(yh + (size_t)r0 * CI + o)       = pack_bf2(h0, h1);
            *(u32*)(yl + (size_t)r0 * CI + o)       = pack_bf2(v0 - h0, v1 - h1);
            *(u32*)(yh + (size_t)(r0 + 8) * CI + o) = pack_bf2(h2, h3);
            *(u32*)(yl + (size_t)(r0 + 8) * CI + o) = pack_bf2(v2 - h2, v3 - h3);
        }
    }
}

// ===========================================================================
// Kernel 3: out = w_out.y + b + x via mma.sync 3-pass. (unchanged R15)
// ===========================================================================
__global__ __launch_bounds__(256, 1) void out_mma(
    const float* __restrict__ x, const float* __restrict__ bo,
    float* __restrict__ out)
{
    extern __shared__ __align__(1024) char sm[];
    u32 dyn = smem_u32(sm);
    int id = blockIdx.x, b = blockIdx.y;
    int ct = id >> 5, nt = id & 31;
    int tid = threadIdx.x, lane = tid & 31, wid = tid >> 5;
    int gid = lane >> 2, tig = lane & 3;

    const __nv_bfloat16* Ahi = g_wo_hi + (size_t)(ct * 128) * CI;
    const __nv_bfloat16* Alo = g_wo_lo + (size_t)(ct * 128) * CI;
    const __nv_bfloat16* Bhi = g_y_hi + (size_t)b * NN * CI + (size_t)(nt * 128) * CI;
    const __nv_bfloat16* Blo = g_y_lo + (size_t)b * NN * CI + (size_t)(nt * 128) * CI;

    auto stage_load = [&](int kc, int buf) {
        u32 base = dyn + buf * ST_SZ;
        #pragma unroll
        for (int i = 0; i < 4; i++) {
            int idx2 = tid + i * 256;
            int r = idx2 >> 3, c = idx2 & 7;
            u32 o = r * 144 + c * 16;
            cp16(base + o,          Ahi + (size_t)r * CI + kc + c * 8);
            cp16(base + ST_ALO + o, Alo + (size_t)r * CI + kc + c * 8);
            cp16(base + ST_BHI + o, Bhi + (size_t)r * CI + kc + c * 8);
            cp16(base + ST_BLO + o, Blo + (size_t)r * CI + kc + c * 8);
        }
    };

    float acc[16][4];
    #pragma unroll
    for (int nb = 0; nb < 16; nb++)
        #pragma unroll
        for (int j = 0; j < 4; j++) acc[nb][j] = 0.f;

    stage_load(0, 0);
    CP_COMMIT();

    int m0 = wid * 16;
    for (int kc4 = 0; kc4 < 4; kc4++) {
        CP_WAIT0();
        __syncthreads();
        if (kc4 < 3) { stage_load((kc4 + 1) * 64, (kc4 + 1) & 1); CP_COMMIT(); }

        u32 sb = (kc4 & 1) * ST_SZ;
        #pragma unroll
        for (int ks = 0; ks < 4; ks++) {
            u32 a0 = sb + (m0 + gid) * 144 + (ks * 16 + 2 * tig) * 2;
            u32 ah[4], al[4];
            ah[0] = *(const u32*)(sm + a0);
            ah[1] = *(const u32*)(sm + a0 + 8 * 144);
            ah[2] = *(const u32*)(sm + a0 + 16);
            ah[3] = *(const u32*)(sm + a0 + 8 * 144 + 16);
            al[0] = *(const u32*)(sm + a0 + ST_ALO);
            al[1] = *(const u32*)(sm + a0 + ST_ALO + 8 * 144);
            al[2] = *(const u32*)(sm + a0 + ST_ALO + 16);
            al[3] = *(const u32*)(sm + a0 + ST_ALO + 8 * 144 + 16);
            #pragma unroll
            for (int nb = 0; nb < 16; nb++) {
                u32 bo2 = sb + ST_BHI + (nb * 8 + gid) * 144 + (ks * 16 + 2 * tig) * 2;
                u32 bh[2], bl[2];
                bh[0] = *(const u32*)(sm + bo2);
                bh[1] = *(const u32*)(sm + bo2 + 16);
                bl[0] = *(const u32*)(sm + bo2 + (ST_BLO - ST_BHI));
                bl[1] = *(const u32*)(sm + bo2 + (ST_BLO - ST_BHI) + 16);
                mma_bf16(acc[nb], ah, bh);
                mma_bf16(acc[nb], ah, bl);
                mma_bf16(acc[nb], al, bh);
            }
        }
    }

    const float* xb = x + (size_t)b * CC * NN;
    float* ob = out + (size_t)b * CC * NN;
    int c0r = ct * 128 + m0 + gid;
    float bc0 = bo[c0r], bc8 = bo[c0r + 8];
    #pragma unroll
    for (int nb = 0; nb < 16; nb++) {
        int n = nt * 128 + nb * 8 + 2 * tig;
        float2 xv0 = *(const float2*)(xb + (size_t)c0r * NN + n);
        float2 xv8 = *(const float2*)(xb + (size_t)(c0r + 8) * NN + n);
        float2 v0 = { acc[nb][0] + bc0 + xv0.x, acc[nb][1] + bc0 + xv0.y };
        float2 v8 = { acc[nb][2] + bc8 + xv8.x, acc[nb][3] + bc8 + xv8.y };
        *(float2*)(ob + (size_t)c0r * NN + n)       = v0;
        *(float2*)(ob + (size_t)(c0r + 8) * NN + n) = v8;
    }
}

extern "C" void kernel_launch(void* const* d_in, const int* in_sizes, int n_in,
                              void* d_out, int out_size)
{
    const float* x  = (const float*)d_in[0];
    const float* wt = (const float*)d_in[1];
    const float* bt = (const float*)d_in[2];
    const float* wp = (const float*)d_in[3];
    const float* bp = (const float*)d_in[4];
    const float* wg = (const float*)d_in[5];
    const float* bg = (const float*)d_in[6];
    const float* wo = (const float*)d_in[7];
    const float* bo = (const float*)d_in[8];
    float* out = (float*)d_out;

    cudaFuncSetAttribute(attn_kernel, cudaFuncAttributeMaxDynamicSharedMemorySize, DYN_SMEM);
    cudaFuncSetAttribute(proj_mma, cudaFuncAttributeMaxDynamicSharedMemorySize, GEMM_SMEM);
    cudaFuncSetAttribute(out_mma, cudaFuncAttributeMaxDynamicSharedMemorySize, GEMM_SMEM);

    xsplit_kernel<<<dim3(NN / 32, CC / 32, BB), 256>>>(x);
    wsplit_kernel<<<dim3(512, 4), 256>>>(wt, wp, wg, wo);

    proj_mma<<<dim3(192, BB), 256, GEMM_SMEM>>>(bt, bp, bg);

    attn_kernel<<<dim3(NN / QT, BB), 256, DYN_SMEM>>>();

    out_mma<<<dim3(128, BB), 256, GEMM_SMEM>>>(x, bo, out);
}